// round 1
// baseline (speedup 1.0000x reference)
#include <cuda_runtime.h>

// LSTM_26972394619494
//
// The reference ends with jax.nn.softmax(logits, axis=1) where axis 1 of the
// (1, 1, 2) logits tensor has size 1. Softmax over a size-1 axis is
// identically 1.0, so the reference output is the constant ones tensor for
// every input — the LSTM recurrence, embeddings, combine, and FC head are all
// dead code. The exact-correct and fastest kernel writes 1.0f to every output
// element in a single tiny launch (d_out is poisoned to 0xAA by the harness,
// so it must be written; the launch is deterministic and graph-capturable).

__global__ void write_ones_kernel(float* __restrict__ out, int n) {
    int i = blockIdx.x * blockDim.x + threadIdx.x;
    if (i < n) out[i] = 1.0f;
}

extern "C" void kernel_launch(void* const* d_in, const int* in_sizes, int n_in,
                              void* d_out, int out_size) {
    (void)d_in; (void)in_sizes; (void)n_in;
    float* out = (float*)d_out;
    int threads = 32;
    int blocks = (out_size + threads - 1) / threads;
    if (blocks < 1) blocks = 1;
    write_ones_kernel<<<blocks, threads>>>(out, out_size);
}

// round 2
// speedup vs baseline: 1.0129x; 1.0129x over previous
#include <cuda_runtime.h>

// LSTM_26972394619494
//
// The reference ends with jax.nn.softmax(logits, axis=1) where axis 1 of the
// (1, 1, 2) logits tensor has size 1. Softmax over a size-1 axis is
// identically 1.0, so the reference output is the constant ones tensor for
// every input — the LSTM recurrence, embeddings, combine, and FC head are all
// dead code. The kernel is therefore a single minimal launch writing 1.0f to
// the output (d_out is poisoned to 0xAA by the harness, so it must be
// written). We are at the graph-replay / launch-overhead floor; this round
// minimizes the kernel node itself: 1 thread, one vectorized 8-byte store,
// no index math, no predication.

__global__ void __launch_bounds__(1) write_ones2_kernel(float2* __restrict__ out) {
    *out = make_float2(1.0f, 1.0f);
}

// Fallback for any out_size != 2 (defensive; metadata says 2 floats).
__global__ void write_ones_n_kernel(float* __restrict__ out, int n) {
    int i = blockIdx.x * blockDim.x + threadIdx.x;
    if (i < n) out[i] = 1.0f;
}

extern "C" void kernel_launch(void* const* d_in, const int* in_sizes, int n_in,
                              void* d_out, int out_size) {
    (void)d_in; (void)in_sizes; (void)n_in;
    if (out_size == 2) {
        write_ones2_kernel<<<1, 1>>>((float2*)d_out);
    } else {
        int threads = 32;
        int blocks = (out_size + threads - 1) / threads;
        if (blocks < 1) blocks = 1;
        write_ones_n_kernel<<<blocks, threads>>>((float*)d_out, out_size);
    }
}